// round 2
// baseline (speedup 1.0000x reference)
#include <cuda_runtime.h>
#include <math.h>

#define D 16
#define K 32
#define COEF_PER_K 153          // 16 rows of (neg_a_i + (i+1) M entries) = 152, + c_k
#define PPT 4                   // points per thread (2 packed pairs)
#define TPB 256
#define TILE (TPB * PPT)
#define LOG_2PI 1.8378770664093453f

typedef unsigned long long u64;

__device__ float g_coef[K * COEF_PER_K];
__device__ float g_partial[8192];

__device__ __forceinline__ u64 fma2(u64 a, u64 b, u64 c) {
    u64 d;
    asm("fma.rn.f32x2 %0, %1, %2, %3;" : "=l"(d) : "l"(a), "l"(b), "l"(c));
    return d;
}
__device__ __forceinline__ u64 pack2(float lo, float hi) {
    u64 d;
    asm("mov.b64 %0, {%1, %2};" : "=l"(d) : "f"(lo), "f"(hi));
    return d;
}
__device__ __forceinline__ void unpack2(u64 v, float& lo, float& hi) {
    asm("mov.b64 {%0, %1}, %2;" : "=f"(lo), "=f"(hi) : "l"(v));
}

// ---------------------------------------------------------------------------
// Setup: one block per component k.
//   cov = A A^T ; chol(cov)=L ; M=L^{-1} ; a=M mu ;
//   c_k = -sum(log L_ii) - 0.5*D*log(2pi) + lw_k^2
// Packed per k: for i in 0..15: [-a_i, M[i][0..i]], then c_k.
// ---------------------------------------------------------------------------
__global__ void mog_setup(const float* __restrict__ means,
                          const float* __restrict__ cov_parts,
                          const float* __restrict__ logw)
{
    const int k = blockIdx.x;
    const int t = threadIdx.x;

    __shared__ float A[D][D];
    __shared__ float C[D][D + 1];
    __shared__ float Mi[D][D + 1];

    if (t < D * D) A[t / D][t % D] = cov_parts[k * D * D + t];
    __syncthreads();

    if (t < D * D) {
        int i = t / D, l = t % D;
        float s = 0.f;
        #pragma unroll
        for (int j = 0; j < D; j++) s += A[i][j] * A[l][j];
        C[i][l] = s;
    }
    __syncthreads();

    for (int j = 0; j < D; j++) {
        if (t == 0) C[j][j] = sqrtf(C[j][j]);
        __syncthreads();
        if (t > j && t < D) C[t][j] = C[t][j] / C[j][j];
        __syncthreads();
        if (t > j && t < D) {
            for (int l = j + 1; l <= t; l++) C[t][l] -= C[t][j] * C[l][j];
        }
        __syncthreads();
    }

    if (t < D) {
        int c = t;
        for (int i = 0; i < c; i++) Mi[i][c] = 0.f;
        Mi[c][c] = 1.f / C[c][c];
        for (int i = c + 1; i < D; i++) {
            float s = 0.f;
            for (int j = c; j < i; j++) s += C[i][j] * Mi[j][c];
            Mi[i][c] = -s / C[i][i];
        }
    }
    __syncthreads();

    if (t == 0) {
        float logdet = 0.f;
        for (int j = 0; j < D; j++) logdet += logf(C[j][j]);
        float lw = logw[k];
        float ck = -logdet - 0.5f * (float)D * LOG_2PI + lw * lw;

        int pos = k * COEF_PER_K;
        for (int i = 0; i < D; i++) {
            float ai = 0.f;
            for (int j = 0; j <= i; j++) ai += Mi[i][j] * means[k * D + j];
            g_coef[pos++] = -ai;
            for (int j = 0; j <= i; j++) g_coef[pos++] = Mi[i][j];
        }
        g_coef[pos] = ck;
    }
}

// ---------------------------------------------------------------------------
// Main: packed f32x2 path. Each thread holds 4 points as 2 packed pairs.
// Coefficients live in shared memory DUPLICATED into both 32-bit halves so the
// inner loop is pure LDS.64(broadcast) + fma.rn.f32x2 (no per-FMA packing).
// ---------------------------------------------------------------------------
__global__ void __launch_bounds__(TPB)
mog_main(const float* __restrict__ data, int N, int nTiles)
{
    __shared__ float2 sc[K * COEF_PER_K];
    __shared__ float red[TPB];

    for (int i = threadIdx.x; i < K * COEF_PER_K; i += TPB) {
        float c = g_coef[i];
        sc[i] = make_float2(c, c);
    }
    __syncthreads();

    float acc = 0.f;

    for (int tile = blockIdx.x; tile < nTiles; tile += gridDim.x) {
        const int base = tile * TILE + threadIdx.x;

        // load 4 points, pack into 2 pairs
        float x[PPT][D];
        bool  valid[PPT];
        #pragma unroll
        for (int p = 0; p < PPT; p++) {
            int idx = base + p * TPB;
            valid[p] = (idx < N);
            int pt = valid[p] ? idx : (N - 1);
            const float4* src = (const float4*)(data + (size_t)pt * D);
            #pragma unroll
            for (int v = 0; v < 4; v++) {
                float4 f = src[v];
                x[p][v * 4 + 0] = f.x;
                x[p][v * 4 + 1] = f.y;
                x[p][v * 4 + 2] = f.z;
                x[p][v * 4 + 3] = f.w;
            }
        }
        u64 xp0[D], xp1[D];
        #pragma unroll
        for (int j = 0; j < D; j++) {
            xp0[j] = pack2(x[0][j], x[1][j]);
            xp1[j] = pack2(x[2][j], x[3][j]);
        }

        float S0 = 0.f, S1 = 0.f, S2 = 0.f, S3 = 0.f;

        for (int k = 0; k < K; k++) {
            const u64* w = (const u64*)(sc + k * COEF_PER_K);
            u64 q0 = 0ull, q1 = 0ull;

            int off = 0;
            #pragma unroll
            for (int i = 0; i < D; i++) {
                u64 na = w[off++];          // {-a_i, -a_i}
                u64 z0 = na, z1 = na;
                #pragma unroll
                for (int j = 0; j <= i; j++) {
                    u64 m = w[off++];       // {M_ij, M_ij}
                    z0 = fma2(m, xp0[j], z0);
                    z1 = fma2(m, xp1[j], z1);
                }
                q0 = fma2(z0, z0, q0);
                q1 = fma2(z1, z1, q1);
            }
            float ck = ((const float2*)w)[COEF_PER_K - 1].x;
            float qa, qb, qc, qd;
            unpack2(q0, qa, qb);
            unpack2(q1, qc, qd);
            S0 += __expf(fmaf(qa, -0.5f, ck));
            S1 += __expf(fmaf(qb, -0.5f, ck));
            S2 += __expf(fmaf(qc, -0.5f, ck));
            S3 += __expf(fmaf(qd, -0.5f, ck));
        }

        if (valid[0]) acc += __logf(S0);
        if (valid[1]) acc += __logf(S1);
        if (valid[2]) acc += __logf(S2);
        if (valid[3]) acc += __logf(S3);
    }

    red[threadIdx.x] = acc;
    __syncthreads();
    for (int s = TPB / 2; s > 0; s >>= 1) {
        if (threadIdx.x < s) red[threadIdx.x] += red[threadIdx.x + s];
        __syncthreads();
    }
    if (threadIdx.x == 0) g_partial[blockIdx.x] = red[0];
}

// ---------------------------------------------------------------------------
__global__ void mog_final(float* __restrict__ out, int N, int nBlocks)
{
    __shared__ double red[256];
    double s = 0.0;
    for (int i = threadIdx.x; i < nBlocks; i += 256) s += (double)g_partial[i];
    red[threadIdx.x] = s;
    __syncthreads();
    for (int st = 128; st > 0; st >>= 1) {
        if (threadIdx.x < st) red[threadIdx.x] += red[threadIdx.x + st];
        __syncthreads();
    }
    if (threadIdx.x == 0) out[0] = (float)(red[0] / (double)N);
}

// ---------------------------------------------------------------------------
extern "C" void kernel_launch(void* const* d_in, const int* in_sizes, int n_in,
                              void* d_out, int out_size)
{
    const float* data      = (const float*)d_in[0];
    const float* means     = (const float*)d_in[1];
    const float* cov_parts = (const float*)d_in[2];
    const float* logw      = (const float*)d_in[3];
    float* out = (float*)d_out;

    const int N = in_sizes[0] / D;

    mog_setup<<<K, 256>>>(means, cov_parts, logw);

    int nTiles = (N + TILE - 1) / TILE;
    int blocks = nTiles < 1184 ? nTiles : 1184;
    mog_main<<<blocks, TPB>>>(data, N, nTiles);

    mog_final<<<1, 256>>>(out, N, blocks);
}

// round 4
// speedup vs baseline: 2.8577x; 2.8577x over previous
#include <cuda_runtime.h>
#include <math.h>
#include <stdint.h>

#define DDIM 16
#define KCOMP 32
#define STRIDE 164             // padded row stride in 32-bit words (164%32=4: bank-spread)
#define TPB 256
#define LOG_2PI 1.8378770664093453f

__device__ uint32_t g_B[KCOMP * STRIDE];   // W, tf32-rounded, pair-permuted columns
__device__ float g_partial[1024];

__device__ __forceinline__ uint32_t smem_u32(const void* p) {
    uint32_t a;
    asm("{ .reg .u64 t; cvta.to.shared.u64 t, %1; cvt.u32.u64 %0, t; }"
        : "=r"(a) : "l"(p));
    return a;
}
__device__ __forceinline__ uint32_t to_tf32(float v) {
    uint32_t u;
    asm("cvt.rna.tf32.f32 %0, %1;" : "=r"(u) : "f"(v));
    return u;
}
__device__ __forceinline__ void ldsv2(uint32_t& a, uint32_t& b, uint32_t addr) {
    asm volatile("ld.shared.v2.b32 {%0, %1}, [%2];" : "=r"(a), "=r"(b) : "r"(addr));
}
__device__ __forceinline__ void mma_tf32(float* c,
                                         uint32_t a0, uint32_t a1, uint32_t a2, uint32_t a3,
                                         uint32_t b0, uint32_t b1) {
    asm volatile(
        "mma.sync.aligned.m16n8k8.row.col.f32.tf32.tf32.f32 "
        "{%0,%1,%2,%3}, {%4,%5,%6,%7}, {%8,%9}, {%0,%1,%2,%3};"
        : "+f"(c[0]), "+f"(c[1]), "+f"(c[2]), "+f"(c[3])
        : "r"(a0), "r"(a1), "r"(a2), "r"(a3), "r"(b0), "r"(b1));
}

// ---------------------------------------------------------------------------
// Setup: one block per component k.
//   cov=AA^T; L=chol(cov); M=L^{-1}; P=M^T M; b=Pmu;
//   score(x) = sum_{i<=j} w_ij x_i x_j + b.x + const  == W_k . phi(x)
// W row written tf32-rounded into g_B with pair-permuted column order:
//   storage col (s*8+jj): logical i = jj odd ? jj/2+4 : jj/2 ; l = s*8+i.
// ---------------------------------------------------------------------------
__global__ void mog_setup(const float* __restrict__ means,
                          const float* __restrict__ cov_parts,
                          const float* __restrict__ logw)
{
    const int k = blockIdx.x;
    const int t = threadIdx.x;

    __shared__ float A[DDIM][DDIM];
    __shared__ float C[DDIM][DDIM + 1];
    __shared__ float Mi[DDIM][DDIM + 1];
    __shared__ float P[DDIM][DDIM + 1];
    __shared__ float bv[DDIM];
    __shared__ float s_const;

    if (t < DDIM * DDIM) A[t / DDIM][t % DDIM] = cov_parts[k * DDIM * DDIM + t];
    __syncthreads();

    if (t < DDIM * DDIM) {
        int i = t / DDIM, l = t % DDIM;
        float s = 0.f;
        #pragma unroll
        for (int j = 0; j < DDIM; j++) s += A[i][j] * A[l][j];
        C[i][l] = s;
    }
    __syncthreads();

    for (int j = 0; j < DDIM; j++) {
        if (t == 0) C[j][j] = sqrtf(C[j][j]);
        __syncthreads();
        if (t > j && t < DDIM) C[t][j] = C[t][j] / C[j][j];
        __syncthreads();
        if (t > j && t < DDIM) {
            for (int l = j + 1; l <= t; l++) C[t][l] -= C[t][j] * C[l][j];
        }
        __syncthreads();
    }

    if (t < DDIM) {                        // M = L^{-1}, column t
        int c = t;
        for (int i = 0; i < c; i++) Mi[i][c] = 0.f;
        Mi[c][c] = 1.f / C[c][c];
        for (int i = c + 1; i < DDIM; i++) {
            float s = 0.f;
            for (int j = c; j < i; j++) s += C[i][j] * Mi[j][c];
            Mi[i][c] = -s / C[i][i];
        }
    }
    __syncthreads();

    {                                      // P = M^T M
        int i = t >> 4, j = t & 15;
        float s = 0.f;
        #pragma unroll
        for (int l = 0; l < DDIM; l++) s += Mi[l][i] * Mi[l][j];
        P[i][j] = s;
    }
    __syncthreads();

    if (t < DDIM) {                        // b = P mu
        float s = 0.f;
        for (int j = 0; j < DDIM; j++) s += P[t][j] * means[k * DDIM + j];
        bv[t] = s;
    }
    __syncthreads();

    if (t == 0) {
        float muPmu = 0.f;
        for (int i = 0; i < DDIM; i++) muPmu += bv[i] * means[k * DDIM + i];
        float logdet = 0.f;
        for (int j = 0; j < DDIM; j++) logdet += logf(C[j][j]);
        float lw = logw[k];
        s_const = -0.5f * muPmu - logdet - 0.5f * (float)DDIM * LOG_2PI + lw * lw;
    }
    __syncthreads();

    if (t < STRIDE) {
        float coeff = 0.f;
        if (t < 160) {
            int s = t >> 3, jj = t & 7;
            int i = (jj & 1) ? ((jj >> 1) + 4) : (jj >> 1);
            int l = s * 8 + i;
            if (l < 136) {
                int i2 = 0, rem = l;
                while (rem >= DDIM - i2) { rem -= DDIM - i2; i2++; }
                int j2 = i2 + rem;
                coeff = (i2 == j2) ? -0.5f * P[i2][i2] : -P[i2][j2];
            } else if (l < 152) {
                coeff = bv[l - 136];
            } else if (l == 152) {
                coeff = s_const;
            }
        }
        g_B[k * STRIDE + t] = to_tf32(coeff);
    }
}

// ---------------------------------------------------------------------------
// Main: persistent CTAs, 256 threads = 8 independent warps. Warp w owns
// 32 points/iter: builds their 160 tf32 features into its own smem rows,
// then two m16 tiles x 4 n-tiles x 20 k-steps of mma.sync tf32, then
// exp/logsumexp epilogue with quad shuffles. No block-level sync in loop.
// ---------------------------------------------------------------------------
#define EMIT(t, val) do { \
    buf[(t) & 7] = to_tf32(val); \
    if (((t) & 7) == 7) { \
        uint32_t _addr = aRowW + (uint32_t)((t) >> 3) * 32u; \
        asm volatile("st.shared.v4.b32 [%0], {%1,%2,%3,%4};" \
            :: "r"(_addr), "r"(buf[0]), "r"(buf[4]), "r"(buf[1]), "r"(buf[5])); \
        asm volatile("st.shared.v4.b32 [%0+16], {%1,%2,%3,%4};" \
            :: "r"(_addr), "r"(buf[2]), "r"(buf[6]), "r"(buf[3]), "r"(buf[7])); \
    } \
} while (0)

__global__ void __launch_bounds__(TPB, 1)
mog_main(const float* __restrict__ data, int N, int nIt, int grid)
{
    extern __shared__ uint32_t smem[];
    __shared__ float s_red[TPB];

    const int tid  = threadIdx.x;
    const int lane = tid & 31;
    const int warp = tid >> 5;
    const int gr   = lane >> 2;     // 0..7
    const int tg   = lane & 3;      // 0..3

    uint32_t* Bsh = smem + TPB * STRIDE;

    for (int i = tid; i < KCOMP * STRIDE; i += TPB) Bsh[i] = g_B[i];
    __syncthreads();

    const uint32_t featBase = smem_u32(smem);
    const uint32_t bBase    = smem_u32(Bsh);
    const uint32_t aRowW = featBase + (uint32_t)tid * (STRIDE * 4u);
    const uint32_t aT0   = featBase + (uint32_t)(warp * 32 + gr) * (STRIDE * 4u)
                         + (uint32_t)tg * 8u;
    const uint32_t bRd   = bBase + (uint32_t)gr * (STRIDE * 4u) + (uint32_t)tg * 8u;

    float acc = 0.f;

    for (int tileIdx = blockIdx.x; tileIdx < nIt; tileIdx += grid) {
        const int base = tileIdx * 256;

        // ---- load point (clamped) ----
        int idxp = base + tid;
        int pt = idxp < N ? idxp : N - 1;
        const float4* src = (const float4*)(data + (size_t)pt * DDIM);
        float x[DDIM];
        #pragma unroll
        for (int v4 = 0; v4 < 4; v4++) {
            float4 f = src[v4];
            x[v4 * 4 + 0] = f.x; x[v4 * 4 + 1] = f.y;
            x[v4 * 4 + 2] = f.z; x[v4 * 4 + 3] = f.w;
        }

        // ---- build 160 tf32 features (pair-permuted) into own smem row ----
        {
            uint32_t buf[8];
            #pragma unroll
            for (int i = 0; i < DDIM; i++) {
                #pragma unroll
                for (int j = i; j < DDIM; j++) {
                    const int t = i * 16 - (i * (i - 1)) / 2 + (j - i);
                    EMIT(t, x[i] * x[j]);
                }
            }
            #pragma unroll
            for (int j = 0; j < DDIM; j++) EMIT(136 + j, x[j]);
            EMIT(152, 1.0f);
            EMIT(153, 0.f); EMIT(154, 0.f); EMIT(155, 0.f);
            EMIT(156, 0.f); EMIT(157, 0.f); EMIT(158, 0.f); EMIT(159, 0.f);
        }

        __syncwarp();

        // ---- mma: 2 row-tiles x 4 n-tiles x 20 k-steps ----
        float c[2][4][4];
        #pragma unroll
        for (int t2 = 0; t2 < 2; t2++)
            #pragma unroll
            for (int n = 0; n < 4; n++)
                #pragma unroll
                for (int q = 0; q < 4; q++) c[t2][n][q] = 0.f;

        #pragma unroll
        for (int s = 0; s < 20; s++) {
            const uint32_t off = (uint32_t)s * 32u;
            uint32_t a0, a1, a2, a3, d0, d1, d2, d3;
            ldsv2(a0, a2, aT0 + off);
            ldsv2(a1, a3, aT0 + 8u  * (STRIDE * 4u) + off);
            ldsv2(d0, d2, aT0 + 16u * (STRIDE * 4u) + off);
            ldsv2(d1, d3, aT0 + 24u * (STRIDE * 4u) + off);
            #pragma unroll
            for (int n = 0; n < 4; n++) {
                uint32_t b0, b1;
                ldsv2(b0, b1, bRd + (uint32_t)(n * 8) * (STRIDE * 4u) + off);
                mma_tf32(c[0][n], a0, a1, a2, a3, b0, b1);
                mma_tf32(c[1][n], d0, d1, d2, d3, b0, b1);
            }
        }

        // ---- epilogue: logsumexp ----
        #pragma unroll
        for (int t2 = 0; t2 < 2; t2++) {
            float S0 = 0.f, S1 = 0.f;
            #pragma unroll
            for (int n = 0; n < 4; n++) {
                S0 += __expf(c[t2][n][0]) + __expf(c[t2][n][1]);
                S1 += __expf(c[t2][n][2]) + __expf(c[t2][n][3]);
            }
            S0 += __shfl_xor_sync(0xffffffffu, S0, 1);
            S0 += __shfl_xor_sync(0xffffffffu, S0, 2);
            S1 += __shfl_xor_sync(0xffffffffu, S1, 1);
            S1 += __shfl_xor_sync(0xffffffffu, S1, 2);
            if (tg == 0) {
                int r0 = base + warp * 32 + t2 * 16 + gr;
                if (r0 < N)     acc += __logf(S0);
                if (r0 + 8 < N) acc += __logf(S1);
            }
        }
        __syncwarp();
    }

    s_red[tid] = acc;
    __syncthreads();
    for (int s = TPB / 2; s > 0; s >>= 1) {
        if (tid < s) s_red[tid] += s_red[tid + s];
        __syncthreads();
    }
    if (tid == 0) g_partial[blockIdx.x] = s_red[0];
}

// ---------------------------------------------------------------------------
__global__ void mog_final(float* __restrict__ out, int N, int nBlocks)
{
    __shared__ double red[256];
    double s = 0.0;
    for (int i = threadIdx.x; i < nBlocks; i += 256) s += (double)g_partial[i];
    red[threadIdx.x] = s;
    __syncthreads();
    for (int st = 128; st > 0; st >>= 1) {
        if (threadIdx.x < st) red[threadIdx.x] += red[threadIdx.x + st];
        __syncthreads();
    }
    if (threadIdx.x == 0) out[0] = (float)(red[0] / (double)N);
}

// ---------------------------------------------------------------------------
extern "C" void kernel_launch(void* const* d_in, const int* in_sizes, int n_in,
                              void* d_out, int out_size)
{
    const float* data      = (const float*)d_in[0];
    const float* means     = (const float*)d_in[1];
    const float* cov_parts = (const float*)d_in[2];
    const float* logw      = (const float*)d_in[3];
    float* out = (float*)d_out;

    const int N = in_sizes[0] / DDIM;

    int sm = 148;
    cudaDeviceGetAttribute(&sm, cudaDevAttrMultiProcessorCount, 0);
    if (sm > 1024) sm = 1024;

    const int smemBytes = (TPB * STRIDE + KCOMP * STRIDE) * 4;   // ~189 KB
    cudaFuncSetAttribute(mog_main, cudaFuncAttributeMaxDynamicSharedMemorySize, smemBytes);

    mog_setup<<<KCOMP, 256>>>(means, cov_parts, logw);

    const int nIt = (N + 255) / 256;
    mog_main<<<sm, TPB, smemBytes>>>(data, N, nIt, sm);

    mog_final<<<1, 256>>>(out, N, sm);
}

// round 5
// speedup vs baseline: 3.6205x; 1.2669x over previous
#include <cuda_runtime.h>
#include <math.h>
#include <stdint.h>

#define DDIM 16
#define KCOMP 32
#define NSTEPS 26              // 24 product k-steps + 2 linear k-steps (x8 = 208 k)
#define BSTRIDE 216            // B row stride in words; 216%32=24 -> conflict-free LDS.64
#define TPB 128
#define LOG_2PI 1.8378770664093453f

__device__ uint32_t g_B[KCOMP * BSTRIDE];   // W, tf32 bits, pair-permuted cols
__device__ float g_const[KCOMP];
__device__ float g_partial[2048];

__device__ __forceinline__ uint32_t smem_u32(const void* p) {
    uint32_t a;
    asm("{ .reg .u64 t; cvta.to.shared.u64 t, %1; cvt.u32.u64 %0, t; }"
        : "=r"(a) : "l"(p));
    return a;
}
__device__ __forceinline__ uint32_t to_tf32(float v) {
    uint32_t u;
    asm("cvt.rna.tf32.f32 %0, %1;" : "=r"(u) : "f"(v));
    return u;
}
__device__ __forceinline__ void ldsv2(uint32_t& a, uint32_t& b, uint32_t addr) {
    asm volatile("ld.shared.v2.b32 {%0, %1}, [%2];" : "=r"(a), "=r"(b) : "r"(addr));
}
__device__ __forceinline__ void mma_tf32(float* c,
                                         uint32_t a0, uint32_t a1, uint32_t a2, uint32_t a3,
                                         uint32_t b0, uint32_t b1) {
    asm volatile(
        "mma.sync.aligned.m16n8k8.row.col.f32.tf32.tf32.f32 "
        "{%0,%1,%2,%3}, {%4,%5,%6,%7}, {%8,%9}, {%0,%1,%2,%3};"
        : "+f"(c[0]), "+f"(c[1]), "+f"(c[2]), "+f"(c[3])
        : "r"(a0), "r"(a1), "r"(a2), "r"(a3), "r"(b0), "r"(b1));
}

// ---------------------------------------------------------------------------
// Setup: one block per component k.
//   cov=AA^T; L=chol; M=L^{-1}; P=M^T M; b=Pmu;
//   score(x) = sum_{i<=j} w_ij x_i x_j + b.x  (+ const via epilogue)
// B layout: step s (k-cols s*8..s*8+7), storage col jj <-> logical c:
//   c = jj odd ? jj/2+4 : jj/2  (so ldsv2 at word 2*tg gives k=tg, k=tg+4).
// Steps: s<16: i=s>>1, j=(s&1)*8+c ; 16<=s<24: i=s-8, j=8+c (j<i -> weight 0);
//        s=24/25: linear b_j, j=(s-24)*8+c.
// ---------------------------------------------------------------------------
__global__ void mog_setup(const float* __restrict__ means,
                          const float* __restrict__ cov_parts,
                          const float* __restrict__ logw)
{
    const int k = blockIdx.x;
    const int t = threadIdx.x;

    __shared__ float A[DDIM][DDIM];
    __shared__ float C[DDIM][DDIM + 1];
    __shared__ float Mi[DDIM][DDIM + 1];
    __shared__ float P[DDIM][DDIM + 1];
    __shared__ float bv[DDIM];
    __shared__ float s_const;

    if (t < DDIM * DDIM) A[t / DDIM][t % DDIM] = cov_parts[k * DDIM * DDIM + t];
    __syncthreads();

    if (t < DDIM * DDIM) {
        int i = t / DDIM, l = t % DDIM;
        float s = 0.f;
        #pragma unroll
        for (int j = 0; j < DDIM; j++) s += A[i][j] * A[l][j];
        C[i][l] = s;
    }
    __syncthreads();

    for (int j = 0; j < DDIM; j++) {
        if (t == 0) C[j][j] = sqrtf(C[j][j]);
        __syncthreads();
        if (t > j && t < DDIM) C[t][j] = C[t][j] / C[j][j];
        __syncthreads();
        if (t > j && t < DDIM) {
            for (int l = j + 1; l <= t; l++) C[t][l] -= C[t][j] * C[l][j];
        }
        __syncthreads();
    }

    if (t < DDIM) {                        // M = L^{-1}, column t
        int c = t;
        for (int i = 0; i < c; i++) Mi[i][c] = 0.f;
        Mi[c][c] = 1.f / C[c][c];
        for (int i = c + 1; i < DDIM; i++) {
            float s = 0.f;
            for (int j = c; j < i; j++) s += C[i][j] * Mi[j][c];
            Mi[i][c] = -s / C[i][i];
        }
    }
    __syncthreads();

    {                                      // P = M^T M
        int i = t >> 4, j = t & 15;
        float s = 0.f;
        #pragma unroll
        for (int l = 0; l < DDIM; l++) s += Mi[l][i] * Mi[l][j];
        P[i][j] = s;
    }
    __syncthreads();

    if (t < DDIM) {                        // b = P mu
        float s = 0.f;
        for (int j = 0; j < DDIM; j++) s += P[t][j] * means[k * DDIM + j];
        bv[t] = s;
    }
    __syncthreads();

    if (t == 0) {
        float muPmu = 0.f;
        for (int i = 0; i < DDIM; i++) muPmu += bv[i] * means[k * DDIM + i];
        float logdet = 0.f;
        for (int j = 0; j < DDIM; j++) logdet += logf(C[j][j]);
        float lw = logw[k];
        s_const = -0.5f * muPmu - logdet - 0.5f * (float)DDIM * LOG_2PI + lw * lw;
    }
    __syncthreads();

    if (t < BSTRIDE) {
        float coeff = 0.f;
        if (t < NSTEPS * 8) {
            int s = t >> 3, jj = t & 7;
            int c = (jj & 1) ? ((jj >> 1) + 4) : (jj >> 1);
            if (s < 24) {
                int i  = (s < 16) ? (s >> 1) : (s - 8);
                int jb = (s < 16) ? ((s & 1) * 8) : 8;
                int j = jb + c;
                if (j > i)       coeff = -P[i][j];
                else if (j == i) coeff = -0.5f * P[i][i];
            } else {
                coeff = bv[(s - 24) * 8 + c];
            }
        }
        g_B[k * BSTRIDE + t] = to_tf32(coeff);
    }
    if (t == 0) g_const[k] = s_const;
}

// ---------------------------------------------------------------------------
// Main: persistent CTAs, 128 threads = 4 warps, 3 CTAs/SM. Each warp owns 32
// points/iter (two m16 row-tiles). A-fragments are computed DIRECTLY in
// registers from the outer-product feature structure (no smem staging):
//   step s, frag col tg: a = x[i(s)] * xa[lo(s)]  (xa[m] = x[tg+4m]).
// B (32x208 tf32) stays in static smem, conflict-free LDS.64.
// ---------------------------------------------------------------------------
__global__ void __launch_bounds__(TPB, 3)
mog_main(const float* __restrict__ data, int N, int nIt, int grid)
{
    __shared__ uint32_t Bsh[KCOMP * BSTRIDE];
    __shared__ float s_red[TPB];

    const int tid  = threadIdx.x;
    const int lane = tid & 31;
    const int warp = tid >> 5;
    const int gr   = lane >> 2;     // 0..7
    const int tg   = lane & 3;      // 0..3

    for (int i = tid; i < KCOMP * BSTRIDE; i += TPB) Bsh[i] = g_B[i];

    float kc[4][2];
    #pragma unroll
    for (int n = 0; n < 4; n++) {
        kc[n][0] = g_const[n * 8 + 2 * tg];
        kc[n][1] = g_const[n * 8 + 2 * tg + 1];
    }
    __syncthreads();

    const uint32_t bBase = smem_u32(Bsh);
    const uint32_t bRd = bBase + (uint32_t)gr * (BSTRIDE * 4u) + (uint32_t)tg * 8u;

    float acc = 0.f;

    for (int tile = blockIdx.x; tile < nIt; tile += grid) {
        const int base = tile * (TPB) + warp * 32;

        // ---- load 4 points (rows gr, gr+8, gr+16, gr+24), clamped ----
        float x[4][DDIM];
        #pragma unroll
        for (int p = 0; p < 4; p++) {
            int idxp = base + gr + 8 * p;
            int pt = idxp < N ? idxp : N - 1;
            const float4* src = (const float4*)(data + (size_t)pt * DDIM);
            #pragma unroll
            for (int v4 = 0; v4 < 4; v4++) {
                float4 f = src[v4];
                x[p][v4 * 4 + 0] = f.x; x[p][v4 * 4 + 1] = f.y;
                x[p][v4 * 4 + 2] = f.z; x[p][v4 * 4 + 3] = f.w;
            }
        }

        // ---- per-thread column selection: xa[p][m] = x[p][tg + 4m] ----
        float xa[4][4];
        #pragma unroll
        for (int p = 0; p < 4; p++) {
            #pragma unroll
            for (int m = 0; m < 4; m++) {
                float v = x[p][4 * m];
                v = (tg == 1) ? x[p][4 * m + 1] : v;
                v = (tg == 2) ? x[p][4 * m + 2] : v;
                v = (tg == 3) ? x[p][4 * m + 3] : v;
                xa[p][m] = v;
            }
        }

        float c[2][4][4];
        #pragma unroll
        for (int t2 = 0; t2 < 2; t2++)
            #pragma unroll
            for (int n = 0; n < 4; n++)
                #pragma unroll
                for (int q = 0; q < 4; q++) c[t2][n][q] = 0.f;

        // ---- 26 k-steps: register A-fragments + smem B + mma ----
        #pragma unroll
        for (int s = 0; s < NSTEPS; s++) {
            const bool lin = (s >= 24);
            const int ii = (s < 16) ? (s >> 1) : (s - 8);
            const int lo = (s < 16) ? ((s & 1) * 2) : ((s < 24) ? 2 : (s - 24) * 2);
            const int hi = lo + 1;

            uint32_t a[2][4];
            #pragma unroll
            for (int t2 = 0; t2 < 2; t2++) {
                #pragma unroll
                for (int pp = 0; pp < 2; pp++) {
                    const int p = t2 * 2 + pp;
                    float flo = lin ? xa[p][lo] : x[p][ii] * xa[p][lo];
                    float fhi = lin ? xa[p][hi] : x[p][ii] * xa[p][hi];
                    a[t2][pp]     = to_tf32(flo);   // row gr(+8), k = tg
                    a[t2][pp + 2] = to_tf32(fhi);   // row gr(+8), k = tg+4
                }
            }
            #pragma unroll
            for (int n = 0; n < 4; n++) {
                uint32_t b0, b1;
                ldsv2(b0, b1, bRd + (uint32_t)(n * 8) * (BSTRIDE * 4u)
                              + (uint32_t)s * 32u);
                mma_tf32(c[0][n], a[0][0], a[0][1], a[0][2], a[0][3], b0, b1);
                mma_tf32(c[1][n], a[1][0], a[1][1], a[1][2], a[1][3], b0, b1);
            }
        }

        // ---- epilogue: add per-component const, exp, logsumexp ----
        #pragma unroll
        for (int t2 = 0; t2 < 2; t2++) {
            float S0 = 0.f, S1 = 0.f;
            #pragma unroll
            for (int n = 0; n < 4; n++) {
                S0 += __expf(c[t2][n][0] + kc[n][0]) + __expf(c[t2][n][1] + kc[n][1]);
                S1 += __expf(c[t2][n][2] + kc[n][0]) + __expf(c[t2][n][3] + kc[n][1]);
            }
            S0 += __shfl_xor_sync(0xffffffffu, S0, 1);
            S0 += __shfl_xor_sync(0xffffffffu, S0, 2);
            S1 += __shfl_xor_sync(0xffffffffu, S1, 1);
            S1 += __shfl_xor_sync(0xffffffffu, S1, 2);
            if (tg == 0) {
                int r0 = base + t2 * 16 + gr;
                if (r0 < N)     acc += __logf(S0);
                if (r0 + 8 < N) acc += __logf(S1);
            }
        }
    }

    s_red[tid] = acc;
    __syncthreads();
    for (int s = TPB / 2; s > 0; s >>= 1) {
        if (tid < s) s_red[tid] += s_red[tid + s];
        __syncthreads();
    }
    if (tid == 0) g_partial[blockIdx.x] = s_red[0];
}

// ---------------------------------------------------------------------------
__global__ void mog_final(float* __restrict__ out, int N, int nBlocks)
{
    __shared__ double red[256];
    double s = 0.0;
    for (int i = threadIdx.x; i < nBlocks; i += 256) s += (double)g_partial[i];
    red[threadIdx.x] = s;
    __syncthreads();
    for (int st = 128; st > 0; st >>= 1) {
        if (threadIdx.x < st) red[threadIdx.x] += red[threadIdx.x + st];
        __syncthreads();
    }
    if (threadIdx.x == 0) out[0] = (float)(red[0] / (double)N);
}

// ---------------------------------------------------------------------------
extern "C" void kernel_launch(void* const* d_in, const int* in_sizes, int n_in,
                              void* d_out, int out_size)
{
    const float* data      = (const float*)d_in[0];
    const float* means     = (const float*)d_in[1];
    const float* cov_parts = (const float*)d_in[2];
    const float* logw      = (const float*)d_in[3];
    float* out = (float*)d_out;

    const int N = in_sizes[0] / DDIM;

    int sm = 148;
    cudaDeviceGetAttribute(&sm, cudaDevAttrMultiProcessorCount, 0);
    if (sm > 680) sm = 680;

    const int nIt = (N + TPB - 1) / TPB;
    int grid = sm * 3;
    if (grid > nIt) grid = nIt;
    if (grid > 2048) grid = 2048;

    mog_setup<<<KCOMP, 256>>>(means, cov_parts, logw);
    mog_main<<<grid, TPB>>>(data, N, nIt, grid);
    mog_final<<<1, 256>>>(out, N, grid);
}

// round 6
// speedup vs baseline: 5.4689x; 1.5105x over previous
#include <cuda_runtime.h>
#include <cuda_fp16.h>
#include <math.h>
#include <stdint.h>

#define DDIM 16
#define KCOMP 32
#define NSTEPS 13              // fp16 k16 steps: 12 product + 1 linear
#define BST 108                // B words per component column (104 used + pad)
#define TPB 128
#define LOG_2PI 1.8378770664093453f

__device__ uint32_t g_B[KCOMP * BST];   // fp16x2-packed weights
__device__ float g_const[KCOMP];
__device__ float g_partial[2048];

__device__ __forceinline__ uint32_t smem_u32(const void* p) {
    uint32_t a;
    asm("{ .reg .u64 t; cvta.to.shared.u64 t, %1; cvt.u32.u64 %0, t; }"
        : "=r"(a) : "l"(p));
    return a;
}
__device__ __forceinline__ uint32_t pack_h2(float lo, float hi) {
    uint32_t r;
    asm("cvt.rn.f16x2.f32 %0, %1, %2;" : "=r"(r) : "f"(hi), "f"(lo));
    return r;
}
__device__ __forceinline__ void ldsv2(uint32_t& a, uint32_t& b, uint32_t addr) {
    asm volatile("ld.shared.v2.b32 {%0, %1}, [%2];" : "=r"(a), "=r"(b) : "r"(addr));
}
__device__ __forceinline__ void mma_f16(float* c,
                                        uint32_t a0, uint32_t a1, uint32_t a2, uint32_t a3,
                                        uint32_t b0, uint32_t b1) {
    asm volatile(
        "mma.sync.aligned.m16n8k16.row.col.f32.f16.f16.f32 "
        "{%0,%1,%2,%3}, {%4,%5,%6,%7}, {%8,%9}, {%0,%1,%2,%3};"
        : "+f"(c[0]), "+f"(c[1]), "+f"(c[2]), "+f"(c[3])
        : "r"(a0), "r"(a1), "r"(a2), "r"(a3), "r"(b0), "r"(b1));
}

// ---------------------------------------------------------------------------
// Setup: one block per component k.
//   cov=AA^T; L=chol; M=L^{-1}; P=M^T M; b=Pmu;
// Half-step H (k-cols H*8..H*8+7), coefficient for slot (H, c):
//   H<16:      i=H>>1, j=(H&1)*8+c
//   16<=H<24:  i=H-8,  j=8+c
//   H=24/25:   linear b[(H-24)*8+c]
//   (j>i: -P[i][j]; j==i: -0.5*P[i][i]; j<i: 0)
// Packed fp16x2: word (H>>1)*8 + 2w + (H&1)  holds  {coef(H,2w), coef(H,2w+1)}.
// ---------------------------------------------------------------------------
__global__ void mog_setup(const float* __restrict__ means,
                          const float* __restrict__ cov_parts,
                          const float* __restrict__ logw)
{
    const int k = blockIdx.x;
    const int t = threadIdx.x;

    __shared__ float A[DDIM][DDIM];
    __shared__ float C[DDIM][DDIM + 1];
    __shared__ float Mi[DDIM][DDIM + 1];
    __shared__ float P[DDIM][DDIM + 1];
    __shared__ float bv[DDIM];

    if (t < DDIM * DDIM) A[t / DDIM][t % DDIM] = cov_parts[k * DDIM * DDIM + t];
    __syncthreads();

    if (t < DDIM * DDIM) {
        int i = t / DDIM, l = t % DDIM;
        float s = 0.f;
        #pragma unroll
        for (int j = 0; j < DDIM; j++) s += A[i][j] * A[l][j];
        C[i][l] = s;
    }
    __syncthreads();

    for (int j = 0; j < DDIM; j++) {
        if (t == 0) C[j][j] = sqrtf(C[j][j]);
        __syncthreads();
        if (t > j && t < DDIM) C[t][j] = C[t][j] / C[j][j];
        __syncthreads();
        if (t > j && t < DDIM) {
            for (int l = j + 1; l <= t; l++) C[t][l] -= C[t][j] * C[l][j];
        }
        __syncthreads();
    }

    if (t < DDIM) {                        // M = L^{-1}, column t
        int c = t;
        for (int i = 0; i < c; i++) Mi[i][c] = 0.f;
        Mi[c][c] = 1.f / C[c][c];
        for (int i = c + 1; i < DDIM; i++) {
            float s = 0.f;
            for (int j = c; j < i; j++) s += C[i][j] * Mi[j][c];
            Mi[i][c] = -s / C[i][i];
        }
    }
    __syncthreads();

    {                                      // P = M^T M
        int i = t >> 4, j = t & 15;
        float s = 0.f;
        #pragma unroll
        for (int l = 0; l < DDIM; l++) s += Mi[l][i] * Mi[l][j];
        P[i][j] = s;
    }
    __syncthreads();

    if (t < DDIM) {                        // b = P mu
        float s = 0.f;
        for (int j = 0; j < DDIM; j++) s += P[t][j] * means[k * DDIM + j];
        bv[t] = s;
    }
    __syncthreads();

    if (t == 0) {
        float muPmu = 0.f;
        for (int i = 0; i < DDIM; i++) muPmu += bv[i] * means[k * DDIM + i];
        float logdet = 0.f;
        for (int j = 0; j < DDIM; j++) logdet += logf(C[j][j]);
        float lw = logw[k];
        g_const[k] = -0.5f * muPmu - logdet - 0.5f * (float)DDIM * LOG_2PI + lw * lw;
    }
    __syncthreads();

    if (t < 104) {
        const int H = t >> 2, w = t & 3;
        float cf[2];
        #pragma unroll
        for (int m = 0; m < 2; m++) {
            int c = 2 * w + m;
            float coeff = 0.f;
            if (H < 24) {
                int i  = (H < 16) ? (H >> 1) : (H - 8);
                int jb = (H < 16) ? ((H & 1) * 8) : 8;
                int j = jb + c;
                if (j > i)       coeff = -P[i][j];
                else if (j == i) coeff = -0.5f * P[i][i];
            } else {
                coeff = bv[(H - 24) * 8 + c];
            }
            cf[m] = coeff;
        }
        g_B[k * BST + (H >> 1) * 8 + 2 * w + (H & 1)] = pack_h2(cf[0], cf[1]);
    }
}

// ---------------------------------------------------------------------------
// Main: persistent CTAs, 128 threads = 4 warps, 3 CTAs/SM. Warp owns 32
// points/iter (two m16 row-tiles). A-fragments built in registers as fp16x2
// (outer-product structure), B fp16x2 in smem, 13 x m16n8k16 f16 MMA steps.
// ---------------------------------------------------------------------------
__global__ void __launch_bounds__(TPB, 3)
mog_main(const float* __restrict__ data, int N, int nIt, int grid)
{
    __shared__ uint32_t Bsh[KCOMP * BST];
    __shared__ float s_red[TPB];

    const int tid  = threadIdx.x;
    const int lane = tid & 31;
    const int warp = tid >> 5;
    const int gr   = lane >> 2;     // 0..7
    const int tg   = lane & 3;      // 0..3

    for (int i = tid; i < KCOMP * BST; i += TPB) Bsh[i] = g_B[i];

    float kc[4][2];
    #pragma unroll
    for (int n = 0; n < 4; n++) {
        kc[n][0] = g_const[n * 8 + 2 * tg];
        kc[n][1] = g_const[n * 8 + 2 * tg + 1];
    }
    __syncthreads();

    const uint32_t bBase = smem_u32(Bsh);
    const uint32_t bRd = bBase + ((uint32_t)gr * BST + 2u * (uint32_t)tg) * 4u;

    float acc = 0.f;

    for (int tile = blockIdx.x; tile < nIt; tile += grid) {
        const int base = tile * TPB + warp * 32;

        // ---- load 4 points (rows gr, gr+8, gr+16, gr+24), clamped ----
        float x[4][DDIM];
        #pragma unroll
        for (int p = 0; p < 4; p++) {
            int idxp = base + gr + 8 * p;
            int pt = idxp < N ? idxp : N - 1;
            const float4* src = (const float4*)(data + (size_t)pt * DDIM);
            #pragma unroll
            for (int v4 = 0; v4 < 4; v4++) {
                float4 f = src[v4];
                x[p][v4 * 4 + 0] = f.x; x[p][v4 * 4 + 1] = f.y;
                x[p][v4 * 4 + 2] = f.z; x[p][v4 * 4 + 3] = f.w;
            }
        }

        // ---- per-thread column pairs: xs0 = x[2tg], x[2tg+1]; xs1 = +8 ----
        float xs0l[4], xs0h[4], xs1l[4], xs1h[4];
        #pragma unroll
        for (int p = 0; p < 4; p++) {
            float a0 = x[p][0], a1 = x[p][1], b0 = x[p][8], b1 = x[p][9];
            a0 = (tg == 1) ? x[p][2]  : a0;  a1 = (tg == 1) ? x[p][3]  : a1;
            b0 = (tg == 1) ? x[p][10] : b0;  b1 = (tg == 1) ? x[p][11] : b1;
            a0 = (tg == 2) ? x[p][4]  : a0;  a1 = (tg == 2) ? x[p][5]  : a1;
            b0 = (tg == 2) ? x[p][12] : b0;  b1 = (tg == 2) ? x[p][13] : b1;
            a0 = (tg == 3) ? x[p][6]  : a0;  a1 = (tg == 3) ? x[p][7]  : a1;
            b0 = (tg == 3) ? x[p][14] : b0;  b1 = (tg == 3) ? x[p][15] : b1;
            xs0l[p] = a0; xs0h[p] = a1; xs1l[p] = b0; xs1h[p] = b1;
        }

        float c[2][4][4];
        #pragma unroll
        for (int t2 = 0; t2 < 2; t2++)
            #pragma unroll
            for (int n = 0; n < 4; n++)
                #pragma unroll
                for (int q = 0; q < 4; q++) c[t2][n][q] = 0.f;

        // ---- 13 k16-steps: register fp16x2 A-fragments + smem B + mma ----
        #pragma unroll
        for (int s = 0; s < NSTEPS; s++) {
            // A regs: a[t2][0]=row gr(half0), [1]=row gr+8(half0),
            //         [2]=row gr(half1),      [3]=row gr+8(half1)
            uint32_t a[2][4];
            #pragma unroll
            for (int t2 = 0; t2 < 2; t2++) {
                #pragma unroll
                for (int pp = 0; pp < 2; pp++) {
                    const int p = t2 * 2 + pp;
                    float l0, h0, l1, h1;
                    if (s < 8) {            // half0: i=s,jb=0; half1: i=s,jb=8
                        float xi = x[p][s];
                        l0 = xi * xs0l[p]; h0 = xi * xs0h[p];
                        l1 = xi * xs1l[p]; h1 = xi * xs1h[p];
                    } else if (s < 12) {    // half0: i=2s-8; half1: i=2s-7; jb=8
                        float xi0 = x[p][2 * s - 8], xi1 = x[p][2 * s - 7];
                        l0 = xi0 * xs1l[p]; h0 = xi0 * xs1h[p];
                        l1 = xi1 * xs1l[p]; h1 = xi1 * xs1h[p];
                    } else {                // linear: half0 -> xs0, half1 -> xs1
                        l0 = xs0l[p]; h0 = xs0h[p];
                        l1 = xs1l[p]; h1 = xs1h[p];
                    }
                    a[t2][pp]     = pack_h2(l0, h0);
                    a[t2][pp + 2] = pack_h2(l1, h1);
                }
            }
            #pragma unroll
            for (int n = 0; n < 4; n++) {
                uint32_t b0, b1;
                ldsv2(b0, b1, bRd + ((uint32_t)(n * 8) * BST + (uint32_t)s * 8u) * 4u);
                mma_f16(c[0][n], a[0][0], a[0][1], a[0][2], a[0][3], b0, b1);
                mma_f16(c[1][n], a[1][0], a[1][1], a[1][2], a[1][3], b0, b1);
            }
        }

        // ---- epilogue: add per-component const, exp, logsumexp ----
        #pragma unroll
        for (int t2 = 0; t2 < 2; t2++) {
            float S0 = 0.f, S1 = 0.f;
            #pragma unroll
            for (int n = 0; n < 4; n++) {
                S0 += __expf(c[t2][n][0] + kc[n][0]) + __expf(c[t2][n][1] + kc[n][1]);
                S1 += __expf(c[t2][n][2] + kc[n][0]) + __expf(c[t2][n][3] + kc[n][1]);
            }
            S0 += __shfl_xor_sync(0xffffffffu, S0, 1);
            S0 += __shfl_xor_sync(0xffffffffu, S0, 2);
            S1 += __shfl_xor_sync(0xffffffffu, S1, 1);
            S1 += __shfl_xor_sync(0xffffffffu, S1, 2);
            if (tg == 0) {
                int r0 = base + t2 * 16 + gr;
                if (r0 < N)     acc += __logf(S0);
                if (r0 + 8 < N) acc += __logf(S1);
            }
        }
    }

    s_red[tid] = acc;
    __syncthreads();
    for (int s = TPB / 2; s > 0; s >>= 1) {
        if (tid < s) s_red[tid] += s_red[tid + s];
        __syncthreads();
    }
    if (tid == 0) g_partial[blockIdx.x] = s_red[0];
}

// ---------------------------------------------------------------------------
__global__ void mog_final(float* __restrict__ out, int N, int nBlocks)
{
    __shared__ double red[256];
    double s = 0.0;
    for (int i = threadIdx.x; i < nBlocks; i += 256) s += (double)g_partial[i];
    red[threadIdx.x] = s;
    __syncthreads();
    for (int st = 128; st > 0; st >>= 1) {
        if (threadIdx.x < st) red[threadIdx.x] += red[threadIdx.x + st];
        __syncthreads();
    }
    if (threadIdx.x == 0) out[0] = (float)(red[0] / (double)N);
}

// ---------------------------------------------------------------------------
extern "C" void kernel_launch(void* const* d_in, const int* in_sizes, int n_in,
                              void* d_out, int out_size)
{
    const float* data      = (const float*)d_in[0];
    const float* means     = (const float*)d_in[1];
    const float* cov_parts = (const float*)d_in[2];
    const float* logw      = (const float*)d_in[3];
    float* out = (float*)d_out;

    const int N = in_sizes[0] / DDIM;

    int sm = 148;
    cudaDeviceGetAttribute(&sm, cudaDevAttrMultiProcessorCount, 0);
    if (sm > 680) sm = 680;

    const int nIt = (N + TPB - 1) / TPB;
    int grid = sm * 3;
    if (grid > nIt) grid = nIt;
    if (grid > 2048) grid = 2048;

    mog_setup<<<KCOMP, 256>>>(means, cov_parts, logw);
    mog_main<<<grid, TPB>>>(data, N, nIt, grid);
    mog_final<<<1, 256>>>(out, N, grid);
}

// round 7
// speedup vs baseline: 5.8681x; 1.0730x over previous
#include <cuda_runtime.h>
#include <cuda_fp16.h>
#include <math.h>
#include <stdint.h>

#define DDIM 16
#define KCOMP 32
#define NQSTEPS 10             // quad k16 steps (40 chunks)
#define NSTEPS 11              // + 1 linear step
#define BST 104                // B words per component (88 used; 104%32=8 -> CF)
#define TPB 128
#define LOG_2PI 1.8378770664093453f

// chunk tables: chunk c = 4*s + (kk>>2); quad chunks c=0..39, linear 40..43
#define CHUNK_TABLES \
    const int CI[40] = { 0,0,0,0, 1,1,1,1, 2,2,2,2, 3,3,3,3, \
                         4,4,4,5, 5,5,6,6, 6,7,7,7, \
                         8,8,9,9, 10,10,11,11, 12,13,14,15 }; \
    const int CO[40] = { 0,1,2,3, 0,1,2,3, 0,1,2,3, 0,1,2,3, \
                         1,2,3,1, 2,3,1,2, 3,1,2,3, \
                         2,3,2,3, 2,3,2,3, 3,3,3,3 };

__device__ uint32_t g_B[KCOMP * BST];   // fp16x2-packed weights
__device__ float g_const[KCOMP];
__device__ float g_partial[2048];

__device__ __forceinline__ uint32_t smem_u32(const void* p) {
    uint32_t a;
    asm("{ .reg .u64 t; cvta.to.shared.u64 t, %1; cvt.u32.u64 %0, t; }"
        : "=r"(a) : "l"(p));
    return a;
}
__device__ __forceinline__ uint32_t pack_h2(float lo, float hi) {
    uint32_t r;
    asm("cvt.rn.f16x2.f32 %0, %1, %2;" : "=r"(r) : "f"(hi), "f"(lo));
    return r;
}
__device__ __forceinline__ void ldsv2(uint32_t& a, uint32_t& b, uint32_t addr) {
    asm volatile("ld.shared.v2.b32 {%0, %1}, [%2];" : "=r"(a), "=r"(b) : "r"(addr));
}
__device__ __forceinline__ void mma_f16(float* c,
                                        uint32_t a0, uint32_t a1, uint32_t a2, uint32_t a3,
                                        uint32_t b0, uint32_t b1) {
    asm volatile(
        "mma.sync.aligned.m16n8k16.row.col.f32.f16.f16.f32 "
        "{%0,%1,%2,%3}, {%4,%5,%6,%7}, {%8,%9}, {%0,%1,%2,%3};"
        : "+f"(c[0]), "+f"(c[1]), "+f"(c[2]), "+f"(c[3])
        : "r"(a0), "r"(a1), "r"(a2), "r"(a3), "r"(b0), "r"(b1));
}

// ---------------------------------------------------------------------------
// Setup: one block per component k.
//   cov=AA^T; L=chol; M=L^{-1}; P=M^T M; b=Pmu;
// B column (s, kk): chunk c = 4s + (kk>>2); j = CO[c]*4 + (kk&3).
//   s<10: weight = (j>CI[c]) ? -P[i][j] : (j==i ? -0.5P[i][i] : 0)
//   s==10: weight = bv[kk]
// Word layout per step: [p0,h1p0, p1,h1p1, ...]: word s*8 + 2*(c'>>1) + (kk>>3)
// where c' = kk&7 -> thread tg ldsv2 at 2tg gives (k=2tg,2tg+1) and (+8).
// ---------------------------------------------------------------------------
__global__ void mog_setup(const float* __restrict__ means,
                          const float* __restrict__ cov_parts,
                          const float* __restrict__ logw)
{
    const int k = blockIdx.x;
    const int t = threadIdx.x;

    __shared__ float A[DDIM][DDIM];
    __shared__ float C[DDIM][DDIM + 1];
    __shared__ float Mi[DDIM][DDIM + 1];
    __shared__ float P[DDIM][DDIM + 1];
    __shared__ float bv[DDIM];

    if (t < DDIM * DDIM) A[t / DDIM][t % DDIM] = cov_parts[k * DDIM * DDIM + t];
    __syncthreads();

    if (t < DDIM * DDIM) {
        int i = t / DDIM, l = t % DDIM;
        float s = 0.f;
        #pragma unroll
        for (int j = 0; j < DDIM; j++) s += A[i][j] * A[l][j];
        C[i][l] = s;
    }
    __syncthreads();

    for (int j = 0; j < DDIM; j++) {
        if (t == 0) C[j][j] = sqrtf(C[j][j]);
        __syncthreads();
        if (t > j && t < DDIM) C[t][j] = C[t][j] / C[j][j];
        __syncthreads();
        if (t > j && t < DDIM) {
            for (int l = j + 1; l <= t; l++) C[t][l] -= C[t][j] * C[l][j];
        }
        __syncthreads();
    }

    if (t < DDIM) {                        // M = L^{-1}, column t
        int c = t;
        for (int i = 0; i < c; i++) Mi[i][c] = 0.f;
        Mi[c][c] = 1.f / C[c][c];
        for (int i = c + 1; i < DDIM; i++) {
            float s = 0.f;
            for (int j = c; j < i; j++) s += C[i][j] * Mi[j][c];
            Mi[i][c] = -s / C[i][i];
        }
    }
    __syncthreads();

    {                                      // P = M^T M
        int i = t >> 4, j = t & 15;
        float s = 0.f;
        #pragma unroll
        for (int l = 0; l < DDIM; l++) s += Mi[l][i] * Mi[l][j];
        P[i][j] = s;
    }
    __syncthreads();

    if (t < DDIM) {                        // b = P mu
        float s = 0.f;
        for (int j = 0; j < DDIM; j++) s += P[t][j] * means[k * DDIM + j];
        bv[t] = s;
    }
    __syncthreads();

    if (t == 0) {
        float muPmu = 0.f;
        for (int i = 0; i < DDIM; i++) muPmu += bv[i] * means[k * DDIM + i];
        float logdet = 0.f;
        for (int j = 0; j < DDIM; j++) logdet += logf(C[j][j]);
        float lw = logw[k];
        g_const[k] = -0.5f * muPmu - logdet - 0.5f * (float)DDIM * LOG_2PI + lw * lw;
    }
    __syncthreads();

    if (t < NSTEPS * 8) {                  // 88 packed words per component
        CHUNK_TABLES
        const int s  = t >> 3;
        const int r  = t & 7;
        const int wp = r >> 1;             // pair index 0..3
        const int hh = r & 1;              // k-half
        float cf[2];
        #pragma unroll
        for (int e = 0; e < 2; e++) {
            const int kk = hh * 8 + 2 * wp + e;   // k-local 0..15
            float coeff = 0.f;
            if (s < NQSTEPS) {
                const int c = 4 * s + (kk >> 2);
                const int i = CI[c];
                const int j = CO[c] * 4 + (kk & 3);
                if (j > i)       coeff = -P[i][j];
                else if (j == i) coeff = -0.5f * P[i][i];
            } else {
                coeff = bv[kk];
            }
            cf[e] = coeff;
        }
        g_B[k * BST + s * 8 + 2 * wp + hh] = pack_h2(cf[0], cf[1]);
    }
}

// ---------------------------------------------------------------------------
// Main: persistent CTAs, 128 threads = 4 warps, 3 CTAs/SM. Warp owns 32
// points/iter. A-fragments built in registers via chunked outer products
// (11 k16 steps, 88 HMMA/warp-iter); B fp16x2 in smem, conflict-free LDS.64.
// ---------------------------------------------------------------------------
__global__ void __launch_bounds__(TPB, 3)
mog_main(const float* __restrict__ data, int N, int nIt, int grid)
{
    __shared__ uint32_t Bsh[KCOMP * BST];
    __shared__ float s_red[TPB];

    const int tid  = threadIdx.x;
    const int lane = tid & 31;
    const int warp = tid >> 5;
    const int gr   = lane >> 2;     // 0..7
    const int tg   = lane & 3;      // 0..3
    const bool p2  = (tg < 2);
    const bool podd = (tg & 1);

    for (int i = tid; i < KCOMP * BST; i += TPB) Bsh[i] = g_B[i];

    float kc[4][2];
    #pragma unroll
    for (int n = 0; n < 4; n++) {
        kc[n][0] = g_const[n * 8 + 2 * tg];
        kc[n][1] = g_const[n * 8 + 2 * tg + 1];
    }
    __syncthreads();

    const uint32_t bBase = smem_u32(Bsh);
    const uint32_t bRd = bBase + ((uint32_t)gr * BST + 2u * (uint32_t)tg) * 4u;

    float acc = 0.f;

    for (int tile = blockIdx.x; tile < nIt; tile += grid) {
        const int base = tile * TPB + warp * 32;

        // ---- load 4 points (rows gr, gr+8, gr+16, gr+24), clamped ----
        float x[4][DDIM];
        #pragma unroll
        for (int p = 0; p < 4; p++) {
            int idxp = base + gr + 8 * p;
            int pt = idxp < N ? idxp : N - 1;
            const float4* src = (const float4*)(data + (size_t)pt * DDIM);
            #pragma unroll
            for (int v4 = 0; v4 < 4; v4++) {
                float4 f = src[v4];
                x[p][v4 * 4 + 0] = f.x; x[p][v4 * 4 + 1] = f.y;
                x[p][v4 * 4 + 2] = f.z; x[p][v4 * 4 + 3] = f.w;
            }
        }

        // ---- per-thread j-pair selection: xjl/xjh[m] = x[4m + 2(tg&1) (+1)] ----
        float xjl[4][4], xjh[4][4];
        #pragma unroll
        for (int p = 0; p < 4; p++) {
            #pragma unroll
            for (int m = 0; m < 4; m++) {
                xjl[p][m] = podd ? x[p][4 * m + 2] : x[p][4 * m];
                xjh[p][m] = podd ? x[p][4 * m + 3] : x[p][4 * m + 1];
            }
        }

        float c[2][4][4];
        #pragma unroll
        for (int t2 = 0; t2 < 2; t2++)
            #pragma unroll
            for (int n = 0; n < 4; n++)
                #pragma unroll
                for (int q = 0; q < 4; q++) c[t2][n][q] = 0.f;

        // ---- 10 quad k16-steps + 1 linear step ----
        CHUNK_TABLES
        #pragma unroll
        for (int s = 0; s < NQSTEPS; s++) {
            uint32_t a[2][4];
            #pragma unroll
            for (int t2 = 0; t2 < 2; t2++) {
                #pragma unroll
                for (int pp = 0; pp < 2; pp++) {
                    const int p = t2 * 2 + pp;
                    // half0: chunks 4s, 4s+1
                    float xi0 = p2 ? x[p][CI[4 * s]]     : x[p][CI[4 * s + 1]];
                    float l0  = p2 ? xjl[p][CO[4 * s]]   : xjl[p][CO[4 * s + 1]];
                    float h0  = p2 ? xjh[p][CO[4 * s]]   : xjh[p][CO[4 * s + 1]];
                    // half1: chunks 4s+2, 4s+3
                    float xi1 = p2 ? x[p][CI[4 * s + 2]] : x[p][CI[4 * s + 3]];
                    float l1  = p2 ? xjl[p][CO[4 * s + 2]] : xjl[p][CO[4 * s + 3]];
                    float h1  = p2 ? xjh[p][CO[4 * s + 2]] : xjh[p][CO[4 * s + 3]];
                    a[t2][pp]     = pack_h2(xi0 * l0, xi0 * h0);
                    a[t2][pp + 2] = pack_h2(xi1 * l1, xi1 * h1);
                }
            }
            #pragma unroll
            for (int n = 0; n < 4; n++) {
                uint32_t b0, b1;
                ldsv2(b0, b1, bRd + ((uint32_t)(n * 8) * BST + (uint32_t)s * 8u) * 4u);
                mma_f16(c[0][n], a[0][0], a[0][1], a[0][2], a[0][3], b0, b1);
                mma_f16(c[1][n], a[1][0], a[1][1], a[1][2], a[1][3], b0, b1);
            }
        }
        {   // linear step s = 10: a = x_j directly; chunk m: half0 tg>>1, half1 2+(tg>>1)
            uint32_t a[2][4];
            #pragma unroll
            for (int t2 = 0; t2 < 2; t2++) {
                #pragma unroll
                for (int pp = 0; pp < 2; pp++) {
                    const int p = t2 * 2 + pp;
                    float l0 = p2 ? xjl[p][0] : xjl[p][1];
                    float h0 = p2 ? xjh[p][0] : xjh[p][1];
                    float l1 = p2 ? xjl[p][2] : xjl[p][3];
                    float h1 = p2 ? xjh[p][2] : xjh[p][3];
                    a[t2][pp]     = pack_h2(l0, h0);
                    a[t2][pp + 2] = pack_h2(l1, h1);
                }
            }
            #pragma unroll
            for (int n = 0; n < 4; n++) {
                uint32_t b0, b1;
                ldsv2(b0, b1, bRd + ((uint32_t)(n * 8) * BST + 80u) * 4u);
                mma_f16(c[0][n], a[0][0], a[0][1], a[0][2], a[0][3], b0, b1);
                mma_f16(c[1][n], a[1][0], a[1][1], a[1][2], a[1][3], b0, b1);
            }
        }

        // ---- epilogue: add per-component const, exp, logsumexp ----
        #pragma unroll
        for (int t2 = 0; t2 < 2; t2++) {
            float S0 = 0.f, S1 = 0.f;
            #pragma unroll
            for (int n = 0; n < 4; n++) {
                S0 += __expf(c[t2][n][0] + kc[n][0]) + __expf(c[t2][n][1] + kc[n][1]);
                S1 += __expf(c[t2][n][2] + kc[n][0]) + __expf(c[t2][n][3] + kc[n][1]);
            }
            S0 += __shfl_xor_sync(0xffffffffu, S0, 1);
            S0 += __shfl_xor_sync(0xffffffffu, S0, 2);
            S1 += __shfl_xor_sync(0xffffffffu, S1, 1);
            S1 += __shfl_xor_sync(0xffffffffu, S1, 2);
            if (tg == 0) {
                int r0 = base + t2 * 16 + gr;
                if (r0 < N)     acc += __logf(S0);
                if (r0 + 8 < N) acc += __logf(S1);
            }
        }
    }

    s_red[tid] = acc;
    __syncthreads();
    for (int s = TPB / 2; s > 0; s >>= 1) {
        if (tid < s) s_red[tid] += s_red[tid + s];
        __syncthreads();
    }
    if (tid == 0) g_partial[blockIdx.x] = s_red[0];
}

// ---------------------------------------------------------------------------
__global__ void mog_final(float* __restrict__ out, int N, int nBlocks)
{
    __shared__ double red[256];
    double s = 0.0;
    for (int i = threadIdx.x; i < nBlocks; i += 256) s += (double)g_partial[i];
    red[threadIdx.x] = s;
    __syncthreads();
    for (int st = 128; st > 0; st >>= 1) {
        if (threadIdx.x < st) red[threadIdx.x] += red[threadIdx.x + st];
        __syncthreads();
    }
    if (threadIdx.x == 0) out[0] = (float)(red[0] / (double)N);
}

// ---------------------------------------------------------------------------
extern "C" void kernel_launch(void* const* d_in, const int* in_sizes, int n_in,
                              void* d_out, int out_size)
{
    const float* data      = (const float*)d_in[0];
    const float* means     = (const float*)d_in[1];
    const float* cov_parts = (const float*)d_in[2];
    const float* logw      = (const float*)d_in[3];
    float* out = (float*)d_out;

    const int N = in_sizes[0] / DDIM;

    int sm = 148;
    cudaDeviceGetAttribute(&sm, cudaDevAttrMultiProcessorCount, 0);
    if (sm > 680) sm = 680;

    const int nIt = (N + TPB - 1) / TPB;
    int grid = sm * 3;
    if (grid > nIt) grid = nIt;
    if (grid > 2048) grid = 2048;

    mog_setup<<<KCOMP, 256>>>(means, cov_parts, logw);
    mog_main<<<grid, TPB>>>(data, N, nIt, grid);
    mog_final<<<1, 256>>>(out, N, grid);
}

// round 8
// speedup vs baseline: 6.7005x; 1.1418x over previous
#include <cuda_runtime.h>
#include <cuda_fp16.h>
#include <math.h>
#include <stdint.h>

#define DDIM 16
#define KCOMP 32
#define NQSTEPS 10             // quad k16 steps (40 chunks)
#define NSTEPS 11              // + 1 linear step
#define BST 104                // B words per component (88 used; 104%32=8 -> CF)
#define TPB 128
#define XBUF (TPB * DDIM)      // floats per staging buffer
#define LOG_2PI 1.8378770664093453f

// chunk tables: chunk c = 4*s + (kk>>2); quad chunks c=0..39, linear 40..43
#define CHUNK_TABLES \
    const int CI[40] = { 0,0,0,0, 1,1,1,1, 2,2,2,2, 3,3,3,3, \
                         4,4,4,5, 5,5,6,6, 6,7,7,7, \
                         8,8,9,9, 10,10,11,11, 12,13,14,15 }; \
    const int CO[40] = { 0,1,2,3, 0,1,2,3, 0,1,2,3, 0,1,2,3, \
                         1,2,3,1, 2,3,1,2, 3,1,2,3, \
                         2,3,2,3, 2,3,2,3, 3,3,3,3 };

__device__ uint32_t g_B[KCOMP * BST];   // fp16x2-packed weights
__device__ float g_const[KCOMP];
__device__ float g_partial[2048];

__device__ __forceinline__ uint32_t smem_u32(const void* p) {
    uint32_t a;
    asm("{ .reg .u64 t; cvta.to.shared.u64 t, %1; cvt.u32.u64 %0, t; }"
        : "=r"(a) : "l"(p));
    return a;
}
__device__ __forceinline__ uint32_t pack_h2(float lo, float hi) {
    uint32_t r;
    asm("cvt.rn.f16x2.f32 %0, %1, %2;" : "=r"(r) : "f"(hi), "f"(lo));
    return r;
}
__device__ __forceinline__ void ldsv2(uint32_t& a, uint32_t& b, uint32_t addr) {
    asm volatile("ld.shared.v2.b32 {%0, %1}, [%2];" : "=r"(a), "=r"(b) : "r"(addr));
}
__device__ __forceinline__ void mma_f16(float* c,
                                        uint32_t a0, uint32_t a1, uint32_t a2, uint32_t a3,
                                        uint32_t b0, uint32_t b1) {
    asm volatile(
        "mma.sync.aligned.m16n8k16.row.col.f32.f16.f16.f32 "
        "{%0,%1,%2,%3}, {%4,%5,%6,%7}, {%8,%9}, {%0,%1,%2,%3};"
        : "+f"(c[0]), "+f"(c[1]), "+f"(c[2]), "+f"(c[3])
        : "r"(a0), "r"(a1), "r"(a2), "r"(a3), "r"(b0), "r"(b1));
}
__device__ __forceinline__ void cp16(uint32_t dst, const void* src) {
    asm volatile("cp.async.ca.shared.global [%0], [%1], 16;"
                 :: "r"(dst), "l"(src) : "memory");
}

// ---------------------------------------------------------------------------
// Setup: one block per component k. Fast ops: rsqrt reciprocal-diag, __logf,
// parallel logdet. Same math: cov=AA^T; L=chol; M=L^{-1}; P=M^T M; b=Pmu.
// ---------------------------------------------------------------------------
__global__ void mog_setup(const float* __restrict__ means,
                          const float* __restrict__ cov_parts,
                          const float* __restrict__ logw)
{
    const int k = blockIdx.x;
    const int t = threadIdx.x;

    __shared__ float A[DDIM][DDIM];
    __shared__ float C[DDIM][DDIM + 1];
    __shared__ float Mi[DDIM][DDIM + 1];
    __shared__ float P[DDIM][DDIM + 1];
    __shared__ float bv[DDIM];
    __shared__ float rdg[DDIM];
    __shared__ float lgs[DDIM];

    if (t < DDIM * DDIM) A[t / DDIM][t % DDIM] = cov_parts[k * DDIM * DDIM + t];
    __syncthreads();

    if (t < DDIM * DDIM) {
        int i = t / DDIM, l = t % DDIM;
        float s = 0.f;
        #pragma unroll
        for (int j = 0; j < DDIM; j++) s += A[i][j] * A[l][j];
        C[i][l] = s;
    }
    __syncthreads();

    for (int j = 0; j < DDIM; j++) {
        if (t == 0) {
            float d = C[j][j];
            float rs = rsqrtf(d);
            rdg[j] = rs;
            C[j][j] = d * rs;          // = sqrt(d)
        }
        __syncthreads();
        if (t > j && t < DDIM) C[t][j] *= rdg[j];
        __syncthreads();
        if (t > j && t < DDIM) {
            for (int l = j + 1; l <= t; l++) C[t][l] -= C[t][j] * C[l][j];
        }
        __syncthreads();
    }

    if (t < DDIM) {                        // M = L^{-1}, column t
        int c = t;
        for (int i = 0; i < c; i++) Mi[i][c] = 0.f;
        Mi[c][c] = rdg[c];
        for (int i = c + 1; i < DDIM; i++) {
            float s = 0.f;
            for (int j = c; j < i; j++) s += C[i][j] * Mi[j][c];
            Mi[i][c] = -s * rdg[i];
        }
        lgs[t] = __logf(C[t][t]);
    }
    __syncthreads();

    {                                      // P = M^T M
        int i = t >> 4, j = t & 15;
        float s = 0.f;
        #pragma unroll
        for (int l = 0; l < DDIM; l++) s += Mi[l][i] * Mi[l][j];
        P[i][j] = s;
    }
    __syncthreads();

    if (t < DDIM) {                        // b = P mu
        float s = 0.f;
        for (int j = 0; j < DDIM; j++) s += P[t][j] * means[k * DDIM + j];
        bv[t] = s;
    }
    __syncthreads();

    if (t == 0) {
        float muPmu = 0.f, logdet = 0.f;
        #pragma unroll
        for (int i = 0; i < DDIM; i++) {
            muPmu += bv[i] * means[k * DDIM + i];
            logdet += lgs[i];
        }
        float lw = logw[k];
        g_const[k] = -0.5f * muPmu - logdet - 0.5f * (float)DDIM * LOG_2PI + lw * lw;
    }
    __syncthreads();

    if (t < NSTEPS * 8) {                  // 88 packed words per component
        CHUNK_TABLES
        const int s  = t >> 3;
        const int r  = t & 7;
        const int wp = r >> 1;
        const int hh = r & 1;
        float cf[2];
        #pragma unroll
        for (int e = 0; e < 2; e++) {
            const int kk = hh * 8 + 2 * wp + e;
            float coeff = 0.f;
            if (s < NQSTEPS) {
                const int c = 4 * s + (kk >> 2);
                const int i = CI[c];
                const int j = CO[c] * 4 + (kk & 3);
                if (j > i)       coeff = -P[i][j];
                else if (j == i) coeff = -0.5f * P[i][i];
            } else {
                coeff = bv[kk];
            }
            cf[e] = coeff;
        }
        g_B[k * BST + s * 8 + 2 * wp + hh] = pack_h2(cf[0], cf[1]);
    }
}

// ---------------------------------------------------------------------------
// Main: persistent CTAs, 128 threads = 4 warps, 3 CTAs/SM. Warp owns 32
// points/iter. 2-deep cp.async pipeline stages the NEXT tile's points into
// warp-private smem while the current MMA phase runs; A-fragments built in
// registers (11 k16 steps, 88 HMMA/warp-iter); B fp16x2 in smem CF LDS.64.
// ---------------------------------------------------------------------------
__global__ void __launch_bounds__(TPB, 3)
mog_main(const float* __restrict__ data, int N, int nIt, int grid)
{
    __shared__ uint32_t Bsh[KCOMP * BST];
    __shared__ float sx[2][XBUF];
    __shared__ float s_red[TPB];

    const int tid  = threadIdx.x;
    const int lane = tid & 31;
    const int warp = tid >> 5;
    const int gr   = lane >> 2;     // 0..7
    const int tg   = lane & 3;      // 0..3
    const bool p2  = (tg < 2);
    const bool podd = (tg & 1);

    for (int i = tid; i < KCOMP * BST; i += TPB) Bsh[i] = g_B[i];

    float kc[4][2];
    #pragma unroll
    for (int n = 0; n < 4; n++) {
        kc[n][0] = g_const[n * 8 + 2 * tg];
        kc[n][1] = g_const[n * 8 + 2 * tg + 1];
    }
    __syncthreads();

    const uint32_t bBase = smem_u32(Bsh);
    const uint32_t bRd = bBase + ((uint32_t)gr * BST + 2u * (uint32_t)tg) * 4u;
    const uint32_t sxB  = smem_u32(sx);
    const uint32_t myDst = sxB + (uint32_t)tid * 64u;            // producer slot

    float acc = 0.f;
    int buf = 0;

    // prologue: stage first tile
    {
        int idxp = blockIdx.x * TPB + tid;
        int pt = idxp < N ? idxp : N - 1;
        const char* g = (const char*)(data + (size_t)pt * DDIM);
        #pragma unroll
        for (int v = 0; v < 4; v++) cp16(myDst + 16u * v, g + 16 * v);
        asm volatile("cp.async.commit_group;" ::: "memory");
    }

    for (int tile = blockIdx.x; tile < nIt; tile += grid) {
        // ---- stage NEXT tile into other buffer ----
        {
            int nxt = tile + grid;
            if (nxt < nIt) {
                int idxp = nxt * TPB + tid;
                int pt = idxp < N ? idxp : N - 1;
                const char* g = (const char*)(data + (size_t)pt * DDIM);
                uint32_t d = myDst + (uint32_t)(buf ^ 1) * (XBUF * 4u);
                #pragma unroll
                for (int v = 0; v < 4; v++) cp16(d + 16u * v, g + 16 * v);
            }
            asm volatile("cp.async.commit_group;" ::: "memory");
        }
        asm volatile("cp.async.wait_group 1;" ::: "memory");
        __syncwarp();

        const int base = tile * TPB + warp * 32;

        // ---- read 4 points from staging (rows gr, gr+8, gr+16, gr+24) ----
        float x[4][DDIM];
        #pragma unroll
        for (int p = 0; p < 4; p++) {
            const float4* s =
                (const float4*)&sx[buf][(warp * 32 + gr + 8 * p) * DDIM];
            #pragma unroll
            for (int v4 = 0; v4 < 4; v4++) {
                float4 f = s[v4];
                x[p][v4 * 4 + 0] = f.x; x[p][v4 * 4 + 1] = f.y;
                x[p][v4 * 4 + 2] = f.z; x[p][v4 * 4 + 3] = f.w;
            }
        }
        __syncwarp();          // all lanes done reading buf before next overwrite
        buf ^= 1;

        // ---- per-thread j-pair selection ----
        float xjl[4][4], xjh[4][4];
        #pragma unroll
        for (int p = 0; p < 4; p++) {
            #pragma unroll
            for (int m = 0; m < 4; m++) {
                xjl[p][m] = podd ? x[p][4 * m + 2] : x[p][4 * m];
                xjh[p][m] = podd ? x[p][4 * m + 3] : x[p][4 * m + 1];
            }
        }

        float c[2][4][4];
        #pragma unroll
        for (int t2 = 0; t2 < 2; t2++)
            #pragma unroll
            for (int n = 0; n < 4; n++)
                #pragma unroll
                for (int q = 0; q < 4; q++) c[t2][n][q] = 0.f;

        // ---- 10 quad k16-steps + 1 linear step ----
        CHUNK_TABLES
        #pragma unroll
        for (int s = 0; s < NQSTEPS; s++) {
            uint32_t a[2][4];
            #pragma unroll
            for (int t2 = 0; t2 < 2; t2++) {
                #pragma unroll
                for (int pp = 0; pp < 2; pp++) {
                    const int p = t2 * 2 + pp;
                    float xi0 = p2 ? x[p][CI[4 * s]]     : x[p][CI[4 * s + 1]];
                    float l0  = p2 ? xjl[p][CO[4 * s]]   : xjl[p][CO[4 * s + 1]];
                    float h0  = p2 ? xjh[p][CO[4 * s]]   : xjh[p][CO[4 * s + 1]];
                    float xi1 = p2 ? x[p][CI[4 * s + 2]] : x[p][CI[4 * s + 3]];
                    float l1  = p2 ? xjl[p][CO[4 * s + 2]] : xjl[p][CO[4 * s + 3]];
                    float h1  = p2 ? xjh[p][CO[4 * s + 2]] : xjh[p][CO[4 * s + 3]];
                    a[t2][pp]     = pack_h2(xi0 * l0, xi0 * h0);
                    a[t2][pp + 2] = pack_h2(xi1 * l1, xi1 * h1);
                }
            }
            #pragma unroll
            for (int n = 0; n < 4; n++) {
                uint32_t b0, b1;
                ldsv2(b0, b1, bRd + ((uint32_t)(n * 8) * BST + (uint32_t)s * 8u) * 4u);
                mma_f16(c[0][n], a[0][0], a[0][1], a[0][2], a[0][3], b0, b1);
                mma_f16(c[1][n], a[1][0], a[1][1], a[1][2], a[1][3], b0, b1);
            }
        }
        {   // linear step s = 10
            uint32_t a[2][4];
            #pragma unroll
            for (int t2 = 0; t2 < 2; t2++) {
                #pragma unroll
                for (int pp = 0; pp < 2; pp++) {
                    const int p = t2 * 2 + pp;
                    float l0 = p2 ? xjl[p][0] : xjl[p][1];
                    float h0 = p2 ? xjh[p][0] : xjh[p][1];
                    float l1 = p2 ? xjl[p][2] : xjl[p][3];
                    float h1 = p2 ? xjh[p][2] : xjh[p][3];
                    a[t2][pp]     = pack_h2(l0, h0);
                    a[t2][pp + 2] = pack_h2(l1, h1);
                }
            }
            #pragma unroll
            for (int n = 0; n < 4; n++) {
                uint32_t b0, b1;
                ldsv2(b0, b1, bRd + ((uint32_t)(n * 8) * BST + 80u) * 4u);
                mma_f16(c[0][n], a[0][0], a[0][1], a[0][2], a[0][3], b0, b1);
                mma_f16(c[1][n], a[1][0], a[1][1], a[1][2], a[1][3], b0, b1);
            }
        }

        // ---- epilogue: add per-component const, exp, logsumexp ----
        #pragma unroll
        for (int t2 = 0; t2 < 2; t2++) {
            float S0 = 0.f, S1 = 0.f;
            #pragma unroll
            for (int n = 0; n < 4; n++) {
                S0 += __expf(c[t2][n][0] + kc[n][0]) + __expf(c[t2][n][1] + kc[n][1]);
                S1 += __expf(c[t2][n][2] + kc[n][0]) + __expf(c[t2][n][3] + kc[n][1]);
            }
            S0 += __shfl_xor_sync(0xffffffffu, S0, 1);
            S0 += __shfl_xor_sync(0xffffffffu, S0, 2);
            S1 += __shfl_xor_sync(0xffffffffu, S1, 1);
            S1 += __shfl_xor_sync(0xffffffffu, S1, 2);
            if (tg == 0) {
                int r0 = base + t2 * 16 + gr;
                if (r0 < N)     acc += __logf(S0);
                if (r0 + 8 < N) acc += __logf(S1);
            }
        }
    }

    s_red[tid] = acc;
    __syncthreads();
    for (int s = TPB / 2; s > 0; s >>= 1) {
        if (tid < s) s_red[tid] += s_red[tid + s];
        __syncthreads();
    }
    if (tid == 0) g_partial[blockIdx.x] = s_red[0];
}

// ---------------------------------------------------------------------------
__global__ void mog_final(float* __restrict__ out, int N, int nBlocks)
{
    __shared__ double red[256];
    double s = 0.0;
    for (int i = threadIdx.x; i < nBlocks; i += 256) s += (double)g_partial[i];
    red[threadIdx.x] = s;
    __syncthreads();
    for (int st = 128; st > 0; st >>= 1) {
        if (threadIdx.x < st) red[threadIdx.x] += red[threadIdx.x + st];
        __syncthreads();
    }
    if (threadIdx.x == 0) out[0] = (float)(red[0] / (double)N);
}

// ---------------------------------------------------------------------------
extern "C" void kernel_launch(void* const* d_in, const int* in_sizes, int n_in,
                              void* d_out, int out_size)
{
    const float* data      = (const float*)d_in[0];
    const float* means     = (const float*)d_in[1];
    const float* cov_parts = (const float*)d_in[2];
    const float* logw      = (const float*)d_in[3];
    float* out = (float*)d_out;

    const int N = in_sizes[0] / DDIM;

    int sm = 148;
    cudaDeviceGetAttribute(&sm, cudaDevAttrMultiProcessorCount, 0);
    if (sm > 680) sm = 680;

    const int nIt = (N + TPB - 1) / TPB;
    int grid = sm * 3;
    if (grid > nIt) grid = nIt;
    if (grid > 2048) grid = 2048;

    mog_setup<<<KCOMP, 256>>>(means, cov_parts, logw);
    mog_main<<<grid, TPB>>>(data, N, nIt, grid);
    mog_final<<<1, 256>>>(out, N, grid);
}

// round 9
// speedup vs baseline: 6.7157x; 1.0023x over previous
#include <cuda_runtime.h>
#include <cuda_fp16.h>
#include <math.h>
#include <stdint.h>

#define DDIM 16
#define KCOMP 32
#define NQSTEPS 10             // quad k16 steps (40 chunks)
#define NSTEPS 11              // + 1 linear step
#define BST 104                // B words per component (88 used; 104%32=8 -> CF)
#define TPB 128
#define XBUF (TPB * DDIM)      // floats per staging buffer
#define LOG_2PI 1.8378770664093453f

// chunk tables: chunk c = 4*s + (kk>>2); quad chunks c=0..39, linear 40..43
#define CHUNK_TABLES \
    const int CI[40] = { 0,0,0,0, 1,1,1,1, 2,2,2,2, 3,3,3,3, \
                         4,4,4,5, 5,5,6,6, 6,7,7,7, \
                         8,8,9,9, 10,10,11,11, 12,13,14,15 }; \
    const int CO[40] = { 0,1,2,3, 0,1,2,3, 0,1,2,3, 0,1,2,3, \
                         1,2,3,1, 2,3,1,2, 3,1,2,3, \
                         2,3,2,3, 2,3,2,3, 3,3,3,3 };

__device__ uint32_t g_B[KCOMP * BST];   // fp16x2-packed weights
__device__ float g_const[KCOMP];
__device__ float g_partial[2048];

__device__ __forceinline__ uint32_t smem_u32(const void* p) {
    uint32_t a;
    asm("{ .reg .u64 t; cvta.to.shared.u64 t, %1; cvt.u32.u64 %0, t; }"
        : "=r"(a) : "l"(p));
    return a;
}
__device__ __forceinline__ uint32_t pack_h2(float lo, float hi) {
    uint32_t r;
    asm("cvt.rn.f16x2.f32 %0, %1, %2;" : "=r"(r) : "f"(hi), "f"(lo));
    return r;
}
__device__ __forceinline__ void ldsv2(uint32_t& a, uint32_t& b, uint32_t addr) {
    asm volatile("ld.shared.v2.b32 {%0, %1}, [%2];" : "=r"(a), "=r"(b) : "r"(addr));
}
__device__ __forceinline__ void mma_f16(float* c,
                                        uint32_t a0, uint32_t a1, uint32_t a2, uint32_t a3,
                                        uint32_t b0, uint32_t b1) {
    asm volatile(
        "mma.sync.aligned.m16n8k16.row.col.f32.f16.f16.f32 "
        "{%0,%1,%2,%3}, {%4,%5,%6,%7}, {%8,%9}, {%0,%1,%2,%3};"
        : "+f"(c[0]), "+f"(c[1]), "+f"(c[2]), "+f"(c[3])
        : "r"(a0), "r"(a1), "r"(a2), "r"(a3), "r"(b0), "r"(b1));
}
__device__ __forceinline__ void cp16(uint32_t dst, const void* src) {
    asm volatile("cp.async.ca.shared.global [%0], [%1], 16;"
                 :: "r"(dst), "l"(src) : "memory");
}

// ---------------------------------------------------------------------------
// Setup: ONE WARP per component (32 blocks x 32 threads). All barriers are
// __syncwarp (~23 cyc) instead of __syncthreads. Operation order identical to
// the 256-thread version: cov=AA^T; chol w/ rsqrt; M=L^{-1}; P=M^T M; b=Pmu;
// identical fp16x2 packing of g_B.
// ---------------------------------------------------------------------------
__global__ void __launch_bounds__(32, 16)
mog_setup(const float* __restrict__ means,
          const float* __restrict__ cov_parts,
          const float* __restrict__ logw)
{
    const int k = blockIdx.x;
    const int t = threadIdx.x;      // 0..31

    __shared__ float A[DDIM][DDIM];
    __shared__ float C[DDIM][DDIM + 1];
    __shared__ float Mi[DDIM][DDIM + 1];
    __shared__ float P[DDIM][DDIM + 1];
    __shared__ float bv[DDIM];
    __shared__ float rdg[DDIM];
    __shared__ float lgs[DDIM];

    // load A: 8 elements per lane
    #pragma unroll
    for (int e = 0; e < 8; e++) {
        int idx = t * 8 + e;
        A[idx >> 4][idx & 15] = cov_parts[k * DDIM * DDIM + idx];
    }
    __syncwarp();

    // C = A A^T: 8 entries per lane
    #pragma unroll
    for (int e = 0; e < 8; e++) {
        int idx = t * 8 + e;
        int i = idx >> 4, l = idx & 15;
        float s = 0.f;
        #pragma unroll
        for (int j = 0; j < DDIM; j++) s += A[i][j] * A[l][j];
        C[i][l] = s;
    }
    __syncwarp();

    // Cholesky (rsqrt reciprocal-diag), warp-synchronous
    for (int j = 0; j < DDIM; j++) {
        if (t == j) {
            float d = C[j][j];
            float rs = rsqrtf(d);
            rdg[j] = rs;
            C[j][j] = d * rs;          // = sqrt(d)
        }
        __syncwarp();
        if (t > j && t < DDIM) C[t][j] *= rdg[j];
        __syncwarp();
        if (t > j && t < DDIM) {
            for (int l = j + 1; l <= t; l++) C[t][l] -= C[t][j] * C[l][j];
        }
        __syncwarp();
    }

    // M = L^{-1}, column t  (+ per-diagonal logs)
    if (t < DDIM) {
        int c = t;
        for (int i = 0; i < c; i++) Mi[i][c] = 0.f;
        Mi[c][c] = rdg[c];
        for (int i = c + 1; i < DDIM; i++) {
            float s = 0.f;
            for (int j = c; j < i; j++) s += C[i][j] * Mi[j][c];
            Mi[i][c] = -s * rdg[i];
        }
        lgs[t] = __logf(C[t][t]);
    }
    __syncwarp();

    // P = M^T M: 8 entries per lane
    #pragma unroll
    for (int e = 0; e < 8; e++) {
        int idx = t * 8 + e;
        int i = idx >> 4, j = idx & 15;
        float s = 0.f;
        #pragma unroll
        for (int l = 0; l < DDIM; l++) s += Mi[l][i] * Mi[l][j];
        P[i][j] = s;
    }
    __syncwarp();

    if (t < DDIM) {                    // b = P mu
        float s = 0.f;
        for (int j = 0; j < DDIM; j++) s += P[t][j] * means[k * DDIM + j];
        bv[t] = s;
    }
    __syncwarp();

    if (t == 0) {
        float muPmu = 0.f, logdet = 0.f;
        #pragma unroll
        for (int i = 0; i < DDIM; i++) {
            muPmu += bv[i] * means[k * DDIM + i];
            logdet += lgs[i];
        }
        float lw = logw[k];
        g_const[k] = -0.5f * muPmu - logdet - 0.5f * (float)DDIM * LOG_2PI + lw * lw;
    }
    __syncwarp();

    // pack 88 fp16x2 words per component (3 rounds of 32 lanes)
    for (int w = t; w < NSTEPS * 8; w += 32) {
        CHUNK_TABLES
        const int s  = w >> 3;
        const int r  = w & 7;
        const int wp = r >> 1;
        const int hh = r & 1;
        float cf[2];
        #pragma unroll
        for (int e = 0; e < 2; e++) {
            const int kk = hh * 8 + 2 * wp + e;
            float coeff = 0.f;
            if (s < NQSTEPS) {
                const int c = 4 * s + (kk >> 2);
                const int i = CI[c];
                const int j = CO[c] * 4 + (kk & 3);
                if (j > i)       coeff = -P[i][j];
                else if (j == i) coeff = -0.5f * P[i][i];
            } else {
                coeff = bv[kk];
            }
            cf[e] = coeff;
        }
        g_B[k * BST + s * 8 + 2 * wp + hh] = pack_h2(cf[0], cf[1]);
    }
}

// ---------------------------------------------------------------------------
// Main: persistent CTAs, 128 threads = 4 warps, 3 CTAs/SM. Warp owns 32
// points/iter. 2-deep cp.async pipeline stages the NEXT tile's points into
// warp-private smem while the current MMA phase runs; A-fragments built in
// registers (11 k16 steps, 88 HMMA/warp-iter); B fp16x2 in smem CF LDS.64.
// ---------------------------------------------------------------------------
__global__ void __launch_bounds__(TPB, 3)
mog_main(const float* __restrict__ data, int N, int nIt, int grid)
{
    __shared__ uint32_t Bsh[KCOMP * BST];
    __shared__ float sx[2][XBUF];
    __shared__ float s_red[TPB];

    const int tid  = threadIdx.x;
    const int lane = tid & 31;
    const int warp = tid >> 5;
    const int gr   = lane >> 2;     // 0..7
    const int tg   = lane & 3;      // 0..3
    const bool p2  = (tg < 2);
    const bool podd = (tg & 1);

    for (int i = tid; i < KCOMP * BST; i += TPB) Bsh[i] = g_B[i];

    float kc[4][2];
    #pragma unroll
    for (int n = 0; n < 4; n++) {
        kc[n][0] = g_const[n * 8 + 2 * tg];
        kc[n][1] = g_const[n * 8 + 2 * tg + 1];
    }
    __syncthreads();

    const uint32_t bBase = smem_u32(Bsh);
    const uint32_t bRd = bBase + ((uint32_t)gr * BST + 2u * (uint32_t)tg) * 4u;
    const uint32_t sxB  = smem_u32(sx);
    const uint32_t myDst = sxB + (uint32_t)tid * 64u;            // producer slot

    float acc = 0.f;
    int buf = 0;

    // prologue: stage first tile
    {
        int idxp = blockIdx.x * TPB + tid;
        int pt = idxp < N ? idxp : N - 1;
        const char* g = (const char*)(data + (size_t)pt * DDIM);
        #pragma unroll
        for (int v = 0; v < 4; v++) cp16(myDst + 16u * v, g + 16 * v);
        asm volatile("cp.async.commit_group;" ::: "memory");
    }

    for (int tile = blockIdx.x; tile < nIt; tile += grid) {
        // ---- stage NEXT tile into other buffer ----
        {
            int nxt = tile + grid;
            if (nxt < nIt) {
                int idxp = nxt * TPB + tid;
                int pt = idxp < N ? idxp : N - 1;
                const char* g = (const char*)(data + (size_t)pt * DDIM);
                uint32_t d = myDst + (uint32_t)(buf ^ 1) * (XBUF * 4u);
                #pragma unroll
                for (int v = 0; v < 4; v++) cp16(d + 16u * v, g + 16 * v);
            }
            asm volatile("cp.async.commit_group;" ::: "memory");
        }
        asm volatile("cp.async.wait_group 1;" ::: "memory");
        __syncwarp();

        const int base = tile * TPB + warp * 32;

        // ---- read 4 points from staging (rows gr, gr+8, gr+16, gr+24) ----
        float x[4][DDIM];
        #pragma unroll
        for (int p = 0; p < 4; p++) {
            const float4* s =
                (const float4*)&sx[buf][(warp * 32 + gr + 8 * p) * DDIM];
            #pragma unroll
            for (int v4 = 0; v4 < 4; v4++) {
                float4 f = s[v4];
                x[p][v4 * 4 + 0] = f.x; x[p][v4 * 4 + 1] = f.y;
                x[p][v4 * 4 + 2] = f.z; x[p][v4 * 4 + 3] = f.w;
            }
        }
        __syncwarp();          // all lanes done reading buf before next overwrite
        buf ^= 1;

        // ---- per-thread j-pair selection ----
        float xjl[4][4], xjh[4][4];
        #pragma unroll
        for (int p = 0; p < 4; p++) {
            #pragma unroll
            for (int m = 0; m < 4; m++) {
                xjl[p][m] = podd ? x[p][4 * m + 2] : x[p][4 * m];
                xjh[p][m] = podd ? x[p][4 * m + 3] : x[p][4 * m + 1];
            }
        }

        float c[2][4][4];
        #pragma unroll
        for (int t2 = 0; t2 < 2; t2++)
            #pragma unroll
            for (int n = 0; n < 4; n++)
                #pragma unroll
                for (int q = 0; q < 4; q++) c[t2][n][q] = 0.f;

        // ---- 10 quad k16-steps + 1 linear step ----
        CHUNK_TABLES
        #pragma unroll
        for (int s = 0; s < NQSTEPS; s++) {
            uint32_t a[2][4];
            #pragma unroll
            for (int t2 = 0; t2 < 2; t2++) {
                #pragma unroll
                for (int pp = 0; pp < 2; pp++) {
                    const int p = t2 * 2 + pp;
                    float xi0 = p2 ? x[p][CI[4 * s]]     : x[p][CI[4 * s + 1]];
                    float l0  = p2 ? xjl[p][CO[4 * s]]   : xjl[p][CO[4 * s + 1]];
                    float h0  = p2 ? xjh[p][CO[4 * s]]   : xjh[p][CO[4 * s + 1]];
                    float xi1 = p2 ? x[p][CI[4 * s + 2]] : x[p][CI[4 * s + 3]];
                    float l1  = p2 ? xjl[p][CO[4 * s + 2]] : xjl[p][CO[4 * s + 3]];
                    float h1  = p2 ? xjh[p][CO[4 * s + 2]] : xjh[p][CO[4 * s + 3]];
                    a[t2][pp]     = pack_h2(xi0 * l0, xi0 * h0);
                    a[t2][pp + 2] = pack_h2(xi1 * l1, xi1 * h1);
                }
            }
            #pragma unroll
            for (int n = 0; n < 4; n++) {
                uint32_t b0, b1;
                ldsv2(b0, b1, bRd + ((uint32_t)(n * 8) * BST + (uint32_t)s * 8u) * 4u);
                mma_f16(c[0][n], a[0][0], a[0][1], a[0][2], a[0][3], b0, b1);
                mma_f16(c[1][n], a[1][0], a[1][1], a[1][2], a[1][3], b0, b1);
            }
        }
        {   // linear step s = 10
            uint32_t a[2][4];
            #pragma unroll
            for (int t2 = 0; t2 < 2; t2++) {
                #pragma unroll
                for (int pp = 0; pp < 2; pp++) {
                    const int p = t2 * 2 + pp;
                    float l0 = p2 ? xjl[p][0] : xjl[p][1];
                    float h0 = p2 ? xjh[p][0] : xjh[p][1];
                    float l1 = p2 ? xjl[p][2] : xjl[p][3];
                    float h1 = p2 ? xjh[p][2] : xjh[p][3];
                    a[t2][pp]     = pack_h2(l0, h0);
                    a[t2][pp + 2] = pack_h2(l1, h1);
                }
            }
            #pragma unroll
            for (int n = 0; n < 4; n++) {
                uint32_t b0, b1;
                ldsv2(b0, b1, bRd + ((uint32_t)(n * 8) * BST + 80u) * 4u);
                mma_f16(c[0][n], a[0][0], a[0][1], a[0][2], a[0][3], b0, b1);
                mma_f16(c[1][n], a[1][0], a[1][1], a[1][2], a[1][3], b0, b1);
            }
        }

        // ---- epilogue: add per-component const, exp, logsumexp ----
        #pragma unroll
        for (int t2 = 0; t2 < 2; t2++) {
            float S0 = 0.f, S1 = 0.f;
            #pragma unroll
            for (int n = 0; n < 4; n++) {
                S0 += __expf(c[t2][n][0] + kc[n][0]) + __expf(c[t2][n][1] + kc[n][1]);
                S1 += __expf(c[t2][n][2] + kc[n][0]) + __expf(c[t2][n][3] + kc[n][1]);
            }
            S0 += __shfl_xor_sync(0xffffffffu, S0, 1);
            S0 += __shfl_xor_sync(0xffffffffu, S0, 2);
            S1 += __shfl_xor_sync(0xffffffffu, S1, 1);
            S1 += __shfl_xor_sync(0xffffffffu, S1, 2);
            if (tg == 0) {
                int r0 = base + t2 * 16 + gr;
                if (r0 < N)     acc += __logf(S0);
                if (r0 + 8 < N) acc += __logf(S1);
            }
        }
    }

    s_red[tid] = acc;
    __syncthreads();
    for (int s = TPB / 2; s > 0; s >>= 1) {
        if (tid < s) s_red[tid] += s_red[tid + s];
        __syncthreads();
    }
    if (tid == 0) g_partial[blockIdx.x] = s_red[0];
}

// ---------------------------------------------------------------------------
__global__ void mog_final(float* __restrict__ out, int N, int nBlocks)
{
    __shared__ double red[256];
    double s = 0.0;
    for (int i = threadIdx.x; i < nBlocks; i += 256) s += (double)g_partial[i];
    red[threadIdx.x] = s;
    __syncthreads();
    for (int st = 128; st > 0; st >>= 1) {
        if (threadIdx.x < st) red[threadIdx.x] += red[threadIdx.x + st];
        __syncthreads();
    }
    if (threadIdx.x == 0) out[0] = (float)(red[0] / (double)N);
}

// ---------------------------------------------------------------------------
extern "C" void kernel_launch(void* const* d_in, const int* in_sizes, int n_in,
                              void* d_out, int out_size)
{
    const float* data      = (const float*)d_in[0];
    const float* means     = (const float*)d_in[1];
    const float* cov_parts = (const float*)d_in[2];
    const float* logw      = (const float*)d_in[3];
    float* out = (float*)d_out;

    const int N = in_sizes[0] / DDIM;

    int sm = 148;
    cudaDeviceGetAttribute(&sm, cudaDevAttrMultiProcessorCount, 0);
    if (sm > 680) sm = 680;

    const int nIt = (N + TPB - 1) / TPB;
    int grid = sm * 3;
    if (grid > nIt) grid = nIt;
    if (grid > 2048) grid = 2048;

    mog_setup<<<KCOMP, 32>>>(means, cov_parts, logw);
    mog_main<<<grid, TPB>>>(data, N, nIt, grid);
    mog_final<<<1, 256>>>(out, N, grid);
}